// round 6
// baseline (speedup 1.0000x reference)
#include <cuda_runtime.h>
#include <math.h>
#include <stdint.h>

// B=64 batches, per batch N=Q*C=400000 fp32 logits.
// Output f32 concat: scores[B*K] | labels[B*K] | segments[B*K*2] | query_ids[B*K].
//
// Single fused kernel, grid (SLICES, B) = (16, 64) = 1024 CTAs:
//  - collect: per-thread cp.async ring (DEPTH=4 x 16B). Hot loop is slim:
//    1 ballot gate per float4-iteration; hits (logit > 2.8, superset of
//    top-100 for N(0,1) data, ~28-sigma margin) pushed warp-aggregated as raw
//    (logit_bits, idx) pairs. Sigmoid/key conversion happens once at flush.
//  - last-arriving slice CTA per batch: exact MSD radix-select over ~1k
//    candidates (cached in the free pipe smem), rank K winners, emit outputs,
//    reset counters for the next graph replay.
//  - exact fallback over the full batch if the candidate set is unusable.

#define MAXB    64
#define CAP     16384
#define SLICES  16
#define TPB     256
#define KMAX    128
#define SBUF    320
#define DEPTH   4
#define SELCACHE (DEPTH * TPB * 2)   // 2048 u64 slots in pipe smem (16KB)

__device__ unsigned long long g_cand[MAXB * CAP];
__device__ int g_cnt[MAXB];
__device__ int g_done[MAXB];

__device__ __forceinline__ unsigned long long make_key(float x, unsigned idx) {
    float s = 1.0f / (1.0f + expf(-x));   // sigmoid ordering == jax (rel_err 8e-9 verified)
    return ((unsigned long long)__float_as_uint(s) << 32) | (unsigned long long)(~idx);
}

__device__ __forceinline__ float max4(float4 v) {
    return fmaxf(fmaxf(v.x, v.y), fmaxf(v.z, v.w));
}

__device__ __forceinline__ uint32_t smem_u32(const void* p) {
    uint32_t a;
    asm("{ .reg .u64 t; cvta.to.shared.u64 t, %1; cvt.u32.u64 %0, t; }" : "=r"(a) : "l"(p));
    return a;
}

__device__ __forceinline__ void cp_async16(uint32_t dst, const float4* src) {
    asm volatile("cp.async.cg.shared.global [%0], [%1], 16;"
                 :: "r"(dst), "l"(src) : "memory");
}
__device__ __forceinline__ void cp_commit() {
    asm volatile("cp.async.commit_group;" ::: "memory");
}
__device__ __forceinline__ void cp_wait_most() {       // allow DEPTH-1 outstanding
    asm volatile("cp.async.wait_group %0;" :: "n"(DEPTH - 1) : "memory");
}
__device__ __forceinline__ void cp_wait_all() {
    asm volatile("cp.async.wait_all;" ::: "memory");
}

// ---- exact top-K selection over candidates (or full logits on fallback) ----
__device__ void do_select(const float* __restrict__ lg,
                          const float* __restrict__ segs,
                          const float* __restrict__ ts,
                          float* __restrict__ out,
                          unsigned long long* s_cache,
                          int b, int B, int Q, int C, int K, int N) {
    int tid = threadIdx.x;
    int lane = tid & 31;
    int wid = tid >> 5;

    int cnt = g_cnt[b];
    bool slow = (cnt < K) || (cnt > CAP);
    int M = slow ? N : cnt;
    const unsigned long long* cand = g_cand + (long long)b * CAP;

    bool cached = (!slow) && (M <= SELCACHE);   // pipe smem is free now
    if (cached) {
        for (int i = tid; i < M; i += TPB) s_cache[i] = cand[i];
    }
    __shared__ int hist[256];
    __shared__ int wtot[8];
    __shared__ unsigned long long sh_prefix;
    __shared__ int sh_remaining;
    if (tid == 0) { sh_prefix = 0ULL; sh_remaining = K; }
    __syncthreads();

    for (int d = 7; d >= 0; --d) {
        hist[tid] = 0;
        __syncthreads();
        int shift = d * 8;
        unsigned long long pmask = (d == 7) ? 0ULL : (~0ULL << (shift + 8));
        unsigned long long prefix = sh_prefix;
        for (int i = tid; i < M; i += TPB) {
            unsigned long long key = cached ? s_cache[i]
                                   : (slow ? make_key(lg[i], (unsigned)i) : cand[i]);
            if ((key & pmask) == prefix)
                atomicAdd(&hist[(int)((key >> shift) & 255)], 1);
        }
        __syncthreads();
        int rem = sh_remaining;
        int h = hist[tid];
        int x = h;                      // suffix-scan within warp
        #pragma unroll
        for (int off = 1; off < 32; off <<= 1) {
            int y = __shfl_down_sync(0xffffffffu, x, off);
            if (lane + off < 32) x += y;
        }
        if (lane == 0) wtot[wid] = x;
        __syncthreads();
        int wsum = 0;
        #pragma unroll
        for (int w = 0; w < 8; w++) if (w > wid) wsum += wtot[w];
        int suffix = x + wsum;          // sum of hist[tid..255]
        if (suffix >= rem && (suffix - h) < rem) {   // unique chosen bin
            sh_prefix = prefix | ((unsigned long long)tid << shift);
            sh_remaining = rem - (suffix - h);
        }
        __syncthreads();
    }
    unsigned long long kth = sh_prefix;   // exact K-th largest key (keys unique)

    __shared__ unsigned long long win[KMAX];
    __shared__ int wc;
    if (tid == 0) wc = 0;
    __syncthreads();
    for (int i = tid; i < M; i += TPB) {
        unsigned long long key = cached ? s_cache[i]
                               : (slow ? make_key(lg[i], (unsigned)i) : cand[i]);
        if (key >= kth) {
            int p = atomicAdd(&wc, 1);
            if (p < KMAX) win[p] = key;
        }
    }
    __syncthreads();

    if (tid < K) {
        unsigned long long k0 = win[tid];
        int rank = 0;
        for (int j = 0; j < K; j++) rank += (win[j] > k0);
        float score = __uint_as_float((unsigned)(k0 >> 32));
        unsigned idx = ~(unsigned)(k0 & 0xffffffffu);
        int q = (int)(idx / (unsigned)C);
        int lbl = (int)(idx - (unsigned)q * (unsigned)C);
        float c = segs[((long long)b * Q + q) * 2 + 0];
        float w = segs[((long long)b * Q + q) * 2 + 1];
        float t = ts[b];
        int BK = B * K;
        int o = b * K + rank;
        out[o]                  = score;
        out[BK + o]             = (float)lbl;
        out[2 * BK + 2 * o]     = (c - 0.5f * w) * t;
        out[2 * BK + 2 * o + 1] = (c + 0.5f * w) * t;
        out[4 * BK + o]         = (float)q;
    }
    __syncthreads();
    if (tid == 0) { g_done[b] = 0; g_cnt[b] = 0; }   // reset for next graph replay
}

__global__ void __launch_bounds__(TPB, 6)
k_main(const float* __restrict__ logits,
       const float* __restrict__ segs,
       const float* __restrict__ ts,
       float* __restrict__ out,
       int B, int Q, int C, int K, int per_cta, float thresh) {
    int b = blockIdx.y;
    int N = Q * C;
    int start = blockIdx.x * per_cta;
    int tid = threadIdx.x;
    int lane = tid & 31;

    __shared__ __align__(16) float4 s_pipe[DEPTH][TPB];   // 16 KB, per-thread columns
    __shared__ float    s_val[SBUF];
    __shared__ unsigned s_idx[SBUF];
    __shared__ int s_cnt;
    __shared__ int s_base;

    if (tid == 0) s_cnt = 0;
    __syncthreads();

    // warp-aggregated push of one component (warp-uniform call site)
    auto push_comp = [&](bool p, float x, unsigned idx) {
        unsigned m = __ballot_sync(0xffffffffu, p);
        if (m) {
            int leader = __ffs(m) - 1;
            int base = 0;
            if (lane == leader) base = atomicAdd(&s_cnt, __popc(m));
            base = __shfl_sync(0xffffffffu, base, leader);
            if (p) {
                int pos = base + __popc(m & ((1u << lane) - 1u));
                if (pos < SBUF) {
                    s_val[pos] = x;
                    s_idx[pos] = idx;
                } else {                              // smem overflow: rare direct global
                    int g = atomicAdd(&g_cnt[b], 1);
                    if (g < CAP) g_cand[b * CAP + g] = make_key(x, idx);
                }
            }
        }
    };

    if (start < N) {
        int count = min(per_cta, N - start);
        const float* base = logits + (long long)b * N + start;
        const float4* src = (const float4*)base;   // start is a multiple of 4 floats
        int n4 = count >> 2;
        int iters = (n4 + TPB - 1) / TPB;
        uint32_t myslot0 = smem_u32(&s_pipe[0][tid]);

        #pragma unroll
        for (int d = 0; d < DEPTH; d++) {          // prologue: fill ring
            int idx = d * TPB + tid;
            if (idx < n4) cp_async16(myslot0 + d * (TPB * 16), src + idx);
            cp_commit();
        }

        for (int k = 0; k < iters; k++) {
            cp_wait_most();                        // group k done -> slot k%DEPTH ready
            int s = k & (DEPTH - 1);
            int idx = k * TPB + tid;
            float4 v = s_pipe[s][tid];
            int nidx = (k + DEPTH) * TPB + tid;    // refill consumed slot immediately
            if (nidx < n4) cp_async16(myslot0 + s * (TPB * 16), src + nidx);
            cp_commit();

            bool valid = (idx < n4);
            bool anyhit = valid && (max4(v) > thresh);
            if (__ballot_sync(0xffffffffu, anyhit)) {   // ~28% of warp-iterations
                unsigned i0 = (unsigned)(start + 4 * idx);
                push_comp(valid && v.x > thresh, v.x, i0);
                push_comp(valid && v.y > thresh, v.y, i0 + 1);
                push_comp(valid && v.z > thresh, v.z, i0 + 2);
                push_comp(valid && v.w > thresh, v.w, i0 + 3);
            }
        }
        cp_wait_all();                             // pipe smem idle before reuse

        // scalar tail (only if count % 4 != 0; never for this shape)
        int cnt4 = n4 << 2;
        int tail = count - cnt4;
        if (tid < tail) {
            float x = base[cnt4 + tid];
            bool p = x > thresh;
            push_comp(p, x, (unsigned)(start + cnt4 + tid));
        }
    }

    // ---- flush: convert staged (logit, idx) -> keys in global ----
    __syncthreads();
    int cnt = min(s_cnt, SBUF);
    if (tid == 0) s_base = atomicAdd(&g_cnt[b], cnt);
    __syncthreads();
    int bs = s_base;
    for (int i2 = tid; i2 < cnt; i2 += TPB) {
        int p = bs + i2;
        if (p < CAP) g_cand[b * CAP + p] = make_key(s_val[i2], s_idx[i2]);
    }

    // ---- arrival: last slice CTA of this batch performs the selection ----
    __threadfence();
    __syncthreads();
    __shared__ int is_last;
    if (tid == 0)
        is_last = (atomicAdd(&g_done[b], 1) == gridDim.x - 1);
    __syncthreads();
    if (is_last) {
        __threadfence();   // acquire: other CTAs' candidate stores visible
        do_select(logits + (long long)b * N, segs, ts, out,
                  (unsigned long long*)&s_pipe[0][0], b, B, Q, C, K, N);
    }
}

extern "C" void kernel_launch(void* const* d_in, const int* in_sizes, int n_in,
                              void* d_out, int out_size) {
    const float* logits = (const float*)d_in[0];   // [B, Q, C] f32
    const float* segs   = (const float*)d_in[1];   // [B, Q, 2] f32
    const float* ts     = (const float*)d_in[2];   // [B] f32

    int B = in_sizes[2];
    int N = in_sizes[0] / B;          // Q * C
    int Q = in_sizes[1] / (2 * B);
    int C = N / Q;
    int K = 100;
    if (K > N) K = N;

    int per_cta = (((N + SLICES - 1) / SLICES) + 3) & ~3;
    dim3 grid(SLICES, B);
    k_main<<<grid, TPB>>>(logits, segs, ts, (float*)d_out, B, Q, C, K, per_cta, 2.8f);
}